// round 2
// baseline (speedup 1.0000x reference)
#include <cuda_runtime.h>
#include <cstdint>

// Problem constants (fixed shapes for this benchmark)
constexpr int B_   = 8;
constexpr int NA   = 4096;
constexpr int NB   = 4096;
constexpr int D_   = 64;

constexpr int ROWS    = 32;             // a-rows per block
constexpr int NSPLIT  = 4;              // candidate splits (one warp each)
constexpr int THREADS = ROWS * NSPLIT;  // 128
constexpr int CPW     = NB / NSPLIT;    // candidates per warp = 1024

__global__ __launch_bounds__(THREADS) void knn3_fused_kernel(
    const float* __restrict__ a_feats,
    const float* __restrict__ b_feats,
    const int*   __restrict__ a_coords,
    const int*   __restrict__ b_coords,
    float*       __restrict__ out)
{
    __shared__ uint32_t sm_cb[NB];                    // packed b coords (16 KB)
    __shared__ uint32_t sm_top[NSPLIT][ROWS][3];      // per-split top-3 keys
    __shared__ float    sm_w[ROWS][3];
    __shared__ int      sm_idx[ROWS][3];

    const int tid   = threadIdx.x;
    const int lane  = tid & 31;          // lane = local a-row
    const int s     = tid >> 5;          // warp id = candidate quarter
    const int batch = blockIdx.y;
    const int row0  = blockIdx.x * ROWS;
    const int row   = row0 + lane;       // global a-row (within batch)

    // ---- load + pack b coords into shared (values < 128 -> 1 byte each) ----
    const int* bc = b_coords + (size_t)batch * NB * 3;
    for (int m = tid; m < NB; m += THREADS) {
        uint32_t x = ((uint32_t)bc[m * 3 + 0]) >> 4;
        uint32_t y = ((uint32_t)bc[m * 3 + 1]) >> 4;
        uint32_t z = ((uint32_t)bc[m * 3 + 2]) >> 4;
        sm_cb[m] = x | (y << 8) | (z << 16);
    }

    // ---- pack this row's a coords ----
    const int* ac = a_coords + ((size_t)batch * NA + row) * 3;
    const uint32_t pa = (((uint32_t)ac[0]) >> 4)
                      | ((((uint32_t)ac[1]) >> 4) << 8)
                      | ((((uint32_t)ac[2]) >> 4) << 16);

    __syncthreads();

    // ---- scan this warp's quarter of candidates; keep 3 smallest keys ----
    // key = (d2 << 12) | m : exact integer d2 + lowest-index tie-break,
    // byte-identical ordering to jax.lax.top_k on -dist.
    uint32_t b0 = 0xFFFFFFFFu, b1 = 0xFFFFFFFFu, b2 = 0xFFFFFFFFu;

    const uint4* cb4 = reinterpret_cast<const uint4*>(sm_cb) + s * (CPW / 4);
    const uint32_t mbase = (uint32_t)(s * CPW);

    #pragma unroll 4
    for (int q = 0; q < CPW / 4; ++q) {
        const uint4 c = cb4[q];                 // broadcast: all lanes same addr
        const uint32_t m = mbase + (uint32_t)(q * 4);

        #pragma unroll
        for (int j = 0; j < 4; ++j) {
            const uint32_t cc = (j == 0) ? c.x : (j == 1) ? c.y : (j == 2) ? c.z : c.w;
            const uint32_t v   = __vabsdiffu4(pa, cc);   // per-byte |da|,|db|,|dz|,0
            const uint32_t d2  = __dp4a(v, v, 0u);       // exact integer distance^2
            const uint32_t key = (d2 << 12) | (m + (uint32_t)j);
            // branchless sorted insert into (b0 <= b1 <= b2)
            const uint32_t t1 = min(b1, max(b0, key));
            const uint32_t t2 = min(b2, max(b1, key));
            b0 = min(b0, key);
            b1 = t1;
            b2 = t2;
        }
    }

    sm_top[s][lane][0] = b0;
    sm_top[s][lane][1] = b1;
    sm_top[s][lane][2] = b2;
    __syncthreads();

    // ---- warp 0 merges the 4 partial top-3 lists per row ----
    if (s == 0) {
        // own (split 0) triple already in b0..b2
        #pragma unroll
        for (int ss = 1; ss < NSPLIT; ++ss) {
            #pragma unroll
            for (int k = 0; k < 3; ++k) {
                const uint32_t key = sm_top[ss][lane][k];
                const uint32_t t1 = min(b1, max(b0, key));
                const uint32_t t2 = min(b2, max(b1, key));
                b0 = min(b0, key);
                b1 = t1;
                b2 = t2;
            }
        }
        const uint32_t keys[3] = { b0, b1, b2 };
        #pragma unroll
        for (int k = 0; k < 3; ++k) {
            const uint32_t d2  = keys[k] >> 12;
            const int      idx = (int)(keys[k] & 0xFFFu);
            const float dist = sqrtf((float)d2) * (1.0f / 128.0f);
            const float w    = fmaxf(0.5f - dist, 0.0f);   // R - clip(dist,0,R)
            sm_idx[lane][k] = idx;
            sm_w[lane][k]   = w;
        }
    }
    __syncthreads();

    // ---- epilogue: out[row] = concat(a_feats[row], sum_k w_k * b_feats[idx_k]) ----
    const float* bf = b_feats + (size_t)batch * NB * D_;
    const float* af = a_feats + ((size_t)batch * NA + row0) * D_;
    float*       o  = out     + ((size_t)batch * NA + row0) * (2 * D_);

    // 32 rows * 128 cols = 1024 float4 chunks; 8 per thread
    for (int c = tid; c < ROWS * 32; c += THREADS) {
        const int r  = c >> 5;       // local row
        const int c4 = c & 31;       // float4 column within the 128-wide row
        float4 val;
        if (c4 < 16) {
            val = reinterpret_cast<const float4*>(af + (size_t)r * D_)[c4];
        } else {
            const int cc = c4 - 16;
            const int   i0 = sm_idx[r][0], i1 = sm_idx[r][1], i2 = sm_idx[r][2];
            const float w0 = sm_w[r][0],  w1 = sm_w[r][1],  w2 = sm_w[r][2];
            const float4 f0 = reinterpret_cast<const float4*>(bf + (size_t)i0 * D_)[cc];
            const float4 f1 = reinterpret_cast<const float4*>(bf + (size_t)i1 * D_)[cc];
            const float4 f2 = reinterpret_cast<const float4*>(bf + (size_t)i2 * D_)[cc];
            val.x = w0 * f0.x + w1 * f1.x + w2 * f2.x;
            val.y = w0 * f0.y + w1 * f1.y + w2 * f2.y;
            val.z = w0 * f0.z + w1 * f1.z + w2 * f2.z;
            val.w = w0 * f0.w + w1 * f1.w + w2 * f2.w;
        }
        reinterpret_cast<float4*>(o + (size_t)r * 2 * D_)[c4] = val;
    }
}

extern "C" void kernel_launch(void* const* d_in, const int* in_sizes, int n_in,
                              void* d_out, int out_size)
{
    const float* a_feats  = (const float*)d_in[0];
    const float* b_feats  = (const float*)d_in[1];
    const int*   a_coords = (const int*)d_in[2];
    const int*   b_coords = (const int*)d_in[3];
    float*       out      = (float*)d_out;

    dim3 grid(NA / ROWS, B_);   // 128 x 8 = 1024 blocks
    knn3_fused_kernel<<<grid, THREADS>>>(a_feats, b_feats, a_coords, b_coords, out);
}

// round 4
// speedup vs baseline: 1.3352x; 1.3352x over previous
#include <cuda_runtime.h>
#include <cstdint>

// Shapes fixed for this benchmark
constexpr int B_ = 8, NA = 4096, NB = 4096, D_ = 64;
constexpr int GC = 8;                 // 16-wide cells per axis -> 8^3 = 512 cells
constexpr int NCELL = GC * GC * GC;   // 512
constexpr int NSC = 64;               // 32-wide supercells -> 4^3
constexpr int CAP = 3072;             // SMEM candidate capacity (avg region ~512)
constexpr int TMAIN = 256;

// Scratch (device globals: no allocation allowed)
__device__ int g_bcount[B_][NCELL];
__device__ int g_bstart[B_][NCELL + 1];
__device__ int g_bcursor[B_][NCELL];
__device__ int g_acount[B_][NSC];
__device__ int g_astart[B_][NSC + 1];
__device__ int g_acursor[B_][NSC];
__device__ uint32_t g_bpack[B_][NB];  // sorted packed (x|y<<8|z<<16), coords already >>4
__device__ int      g_bidx[B_][NB];   // original b index (for gather + tie-break)
__device__ uint32_t g_apack[B_][NA];
__device__ int      g_aidx[B_][NA];   // original a row

__global__ void k_zero() {
    int t = blockIdx.x * blockDim.x + threadIdx.x;
    if (t < B_ * NCELL) (&g_bcount[0][0])[t] = 0;
    if (t < B_ * NSC)   (&g_acount[0][0])[t] = 0;
}

__global__ void k_hist(const int* __restrict__ ac, const int* __restrict__ bc) {
    int t = blockIdx.x * blockDim.x + threadIdx.x;
    if (t < B_ * NB) {
        const int* c = bc + (size_t)t * 3;
        int cx = c[0] >> 8, cy = c[1] >> 8, cz = c[2] >> 8;   // raw -> cell (16 wide)
        atomicAdd(&g_bcount[t >> 12][cx + GC * cy + GC * GC * cz], 1);
    } else if (t < 2 * B_ * NB) {
        int u = t - B_ * NB;
        const int* c = ac + (size_t)u * 3;
        int sx = c[0] >> 9, sy = c[1] >> 9, sz = c[2] >> 9;   // raw -> supercell (32 wide)
        atomicAdd(&g_acount[u >> 12][sx + 4 * sy + 16 * sz], 1);
    }
}

// One block per batch: exclusive scans for b-cells (512) and a-supercells (64)
__global__ void k_scan() {
    const int b = blockIdx.x, t = threadIdx.x;
    __shared__ int buf[2][NCELL];
    int v = g_bcount[b][t];
    buf[0][t] = v;
    int src = 0;
    for (int off = 1; off < NCELL; off <<= 1) {
        __syncthreads();
        int x = buf[src][t];
        if (t >= off) x += buf[src][t - off];
        buf[src ^ 1][t] = x;
        src ^= 1;
    }
    __syncthreads();
    int incl = buf[src][t];
    g_bstart[b][t + 1] = incl;
    g_bcursor[b][t] = incl - v;
    if (t == 0) g_bstart[b][0] = 0;
    __syncthreads();

    int va = 0;
    if (t < NSC) { va = g_acount[b][t]; buf[0][t] = va; }
    src = 0;
    for (int off = 1; off < NSC; off <<= 1) {
        __syncthreads();
        if (t < NSC) {
            int x = buf[src][t];
            if (t >= off) x += buf[src][t - off];
            buf[src ^ 1][t] = x;
        }
        src ^= 1;
    }
    __syncthreads();
    if (t < NSC) {
        int incla = buf[src][t];
        g_astart[b][t + 1] = incla;
        g_acursor[b][t] = incla - va;
        if (t == 0) g_astart[b][0] = 0;
    }
}

__global__ void k_scatter(const int* __restrict__ ac, const int* __restrict__ bc) {
    int t = blockIdx.x * blockDim.x + threadIdx.x;
    if (t < B_ * NB) {
        const int b = t >> 12, m = t & (NB - 1);
        const int* c = bc + (size_t)t * 3;
        uint32_t x = ((uint32_t)c[0]) >> 4, y = ((uint32_t)c[1]) >> 4, z = ((uint32_t)c[2]) >> 4;
        int cell = (int)(x >> 4) + GC * (int)(y >> 4) + GC * GC * (int)(z >> 4);
        int pos = atomicAdd(&g_bcursor[b][cell], 1);
        g_bpack[b][pos] = x | (y << 8) | (z << 16);
        g_bidx[b][pos]  = m;
    } else if (t < 2 * B_ * NB) {
        int u = t - B_ * NB;
        const int b = u >> 12, n = u & (NA - 1);
        const int* c = ac + (size_t)u * 3;
        uint32_t x = ((uint32_t)c[0]) >> 4, y = ((uint32_t)c[1]) >> 4, z = ((uint32_t)c[2]) >> 4;
        int sc = (int)(x >> 5) + 4 * (int)(y >> 5) + 16 * (int)(z >> 5);
        int pos = atomicAdd(&g_acursor[b][sc], 1);
        g_apack[b][pos] = x | (y << 8) | (z << 16);
        g_aidx[b][pos]  = n;
    }
}

__device__ __forceinline__ void insert3(uint32_t key, uint32_t& b0, uint32_t& b1, uint32_t& b2) {
    uint32_t t1 = min(b1, max(b0, key));
    uint32_t t2 = min(b2, max(b1, key));
    b0 = min(b0, key);
    b1 = t1;
    b2 = t2;
}

// grid (NSC, B_, 4), block 256 (8 warps = 8 candidate splits; 32 a-points per set)
__global__ __launch_bounds__(TMAIN) void k_main(
    const float* __restrict__ a_feats, const float* __restrict__ b_feats,
    float* __restrict__ out)
{
    __shared__ uint32_t sm_cp[CAP];
    __shared__ int      sm_ci[CAP];
    __shared__ uint32_t sm_top[8][32][3];
    __shared__ int   sm_i[32][3];
    __shared__ float sm_w[32][3];
    __shared__ int   sm_orow[32];
    __shared__ int   sm_rs[16];
    __shared__ int   sm_ro[17];

    const int b = blockIdx.y, scid = blockIdx.x;
    const int tid = threadIdx.x, lane = tid & 31, w = tid >> 5;

    const int astart = g_astart[b][scid], aend = g_astart[b][scid + 1];
    const int abase0 = astart + blockIdx.z * 32;
    if (abase0 >= aend) return;

    // Candidate region: 4x4x4 cells around the supercell (clipped)
    const int sx = scid & 3, sy = (scid >> 2) & 3, sz = scid >> 4;
    const int x0 = max(0, 2 * sx - 1), x1 = min(GC - 1, 2 * sx + 2);
    const int y0 = max(0, 2 * sy - 1), y1 = min(GC - 1, 2 * sy + 2);
    const int z0 = max(0, 2 * sz - 1), z1 = min(GC - 1, 2 * sz + 2);
    const int ny = y1 - y0 + 1, nz = z1 - z0 + 1, nrun = ny * nz;

    if (tid == 0) {
        int off = 0;
        for (int r = 0; r < nrun; r++) {
            int cy = y0 + r % ny, cz = z0 + r / ny;
            int c0 = x0 + GC * cy + GC * GC * cz;
            int s = g_bstart[b][c0];
            int e = g_bstart[b][c0 + (x1 - x0) + 1];
            sm_rs[r] = s;
            sm_ro[r] = off;
            off += e - s;
        }
        sm_ro[nrun] = off;
    }
    __syncthreads();
    const int total = sm_ro[nrun];
    const int insm  = min(total, CAP);
    for (int r = 0; r < nrun; r++) {
        const int o0 = sm_ro[r], o1 = min(sm_ro[r + 1], insm);
        const int gsrc = sm_rs[r] - o0;
        for (int i = o0 + tid; i < o1; i += TMAIN) {
            sm_cp[i] = g_bpack[b][gsrc + i];
            sm_ci[i] = g_bidx[b][gsrc + i];
        }
    }
    // Pad to a multiple of 4 with entries whose key exceeds any real key
    // (4th byte 0xFF -> d2 >= 65025 > max real d2 48387; also triggers fallback if ever picked)
    const int nq = (insm + 3) >> 2;
    for (int i = insm + tid; i < nq * 4; i += TMAIN) {
        sm_cp[i] = 0xFF000000u;
        sm_ci[i] = 0;
    }
    __syncthreads();

    for (int abase = abase0; abase < aend; abase += (int)gridDim.z * 32) {
        const int ap = abase + lane;
        const bool valid = ap < aend;
        const uint32_t pa = valid ? g_apack[b][ap] : 0u;
        uint32_t b0 = ~0u, b1 = ~0u, b2 = ~0u;

        const uint4* cp4 = (const uint4*)sm_cp;
        const int4*  ci4 = (const int4*)sm_ci;
        for (int q = w; q < nq; q += 8) {
            const uint4 c  = cp4[q];     // broadcast across lanes
            const int4  mi = ci4[q];
            uint32_t v, d2;
            v = __vabsdiffu4(pa, c.x); d2 = __dp4a(v, v, 0u);
            insert3(d2 * 4096u + (uint32_t)mi.x, b0, b1, b2);
            v = __vabsdiffu4(pa, c.y); d2 = __dp4a(v, v, 0u);
            insert3(d2 * 4096u + (uint32_t)mi.y, b0, b1, b2);
            v = __vabsdiffu4(pa, c.z); d2 = __dp4a(v, v, 0u);
            insert3(d2 * 4096u + (uint32_t)mi.z, b0, b1, b2);
            v = __vabsdiffu4(pa, c.w); d2 = __dp4a(v, v, 0u);
            insert3(d2 * 4096u + (uint32_t)mi.w, b0, b1, b2);
        }
        if (total > insm) {  // SMEM overflow remainder: scan straight from global (broadcast)
            for (int r = 0; r < nrun; r++) {
                const int o0 = sm_ro[r], o1 = sm_ro[r + 1];
                const int gsrc = sm_rs[r] - o0;
                for (int i = max(o0, insm) + w; i < o1; i += 8) {
                    const uint32_t cc = g_bpack[b][gsrc + i];
                    const uint32_t mm = (uint32_t)g_bidx[b][gsrc + i];
                    const uint32_t v = __vabsdiffu4(pa, cc);
                    const uint32_t d2 = __dp4a(v, v, 0u);
                    insert3(d2 * 4096u + mm, b0, b1, b2);
                }
            }
        }
        sm_top[w][lane][0] = b0; sm_top[w][lane][1] = b1; sm_top[w][lane][2] = b2;
        __syncthreads();

        if (w == 0) {
            #pragma unroll
            for (int ss = 1; ss < 8; ss++)
                #pragma unroll
                for (int k = 0; k < 3; k++)
                    insert3(sm_top[ss][lane][k], b0, b1, b2);

            // Exactness guarantee: region covers ball(a, 16). If 3rd-best d2 >= 256,
            // fall back to an exact full scan for this lane (astronomically rare).
            if (valid && (b2 >> 12) >= 256u) {
                b0 = b1 = b2 = ~0u;
                for (int m = 0; m < NB; m++) {
                    const uint32_t v = __vabsdiffu4(pa, g_bpack[b][m]);
                    const uint32_t d2 = __dp4a(v, v, 0u);
                    insert3(d2 * 4096u + (uint32_t)g_bidx[b][m], b0, b1, b2);
                }
            }
            const uint32_t keys[3] = {b0, b1, b2};
            #pragma unroll
            for (int k = 0; k < 3; k++) {
                const uint32_t d2 = keys[k] >> 12;
                sm_i[lane][k] = (int)(keys[k] & 0xFFFu);
                const float dist = sqrtf((float)d2) * (1.0f / 128.0f);
                sm_w[lane][k] = fmaxf(0.5f - dist, 0.0f);
            }
            sm_orow[lane] = valid ? g_aidx[b][ap] : 0;
        }
        __syncthreads();

        // Fused epilogue: out[row] = concat(a_feats[row], sum_k w_k * b_feats[i_k])
        const int nval = min(32, aend - abase);
        const float* bf = b_feats + (size_t)b * NB * D_;
        for (int u = tid; u < nval * 32; u += TMAIN) {
            const int r = u >> 5, c4 = u & 31;
            const int orow = sm_orow[r];
            float4 val;
            if (c4 < 16) {
                val = ((const float4*)(a_feats + ((size_t)b * NA + orow) * D_))[c4];
            } else {
                const int cc = c4 - 16;
                const float4 f0 = ((const float4*)(bf + (size_t)sm_i[r][0] * D_))[cc];
                const float4 f1 = ((const float4*)(bf + (size_t)sm_i[r][1] * D_))[cc];
                const float4 f2 = ((const float4*)(bf + (size_t)sm_i[r][2] * D_))[cc];
                const float w0 = sm_w[r][0], w1 = sm_w[r][1], w2 = sm_w[r][2];
                val.x = w0 * f0.x + w1 * f1.x + w2 * f2.x;
                val.y = w0 * f0.y + w1 * f1.y + w2 * f2.y;
                val.z = w0 * f0.z + w1 * f1.z + w2 * f2.z;
                val.w = w0 * f0.w + w1 * f1.w + w2 * f2.w;
            }
            ((float4*)(out + ((size_t)b * NA + orow) * 2 * D_))[c4] = val;
        }
        __syncthreads();  // protect SMEM reuse next a-set
    }
}

extern "C" void kernel_launch(void* const* d_in, const int* in_sizes, int n_in,
                              void* d_out, int out_size)
{
    const float* a_feats  = (const float*)d_in[0];
    const float* b_feats  = (const float*)d_in[1];
    const int*   a_coords = (const int*)d_in[2];
    const int*   b_coords = (const int*)d_in[3];
    float*       out      = (float*)d_out;

    k_zero<<<(B_ * NCELL + 255) / 256, 256>>>();
    k_hist<<<(2 * B_ * NB + 255) / 256, 256>>>(a_coords, b_coords);
    k_scan<<<B_, NCELL>>>();
    k_scatter<<<(2 * B_ * NB + 255) / 256, 256>>>(a_coords, b_coords);
    dim3 grid(NSC, B_, 4);
    k_main<<<grid, TMAIN>>>(a_feats, b_feats, out);
}

// round 5
// speedup vs baseline: 1.4255x; 1.0676x over previous
#include <cuda_runtime.h>
#include <cstdint>

// Shapes fixed for this benchmark
constexpr int B_ = 8, NA = 4096, NB = 4096, D_ = 64;
constexpr int GC = 8;                 // 16-wide cells per axis -> 8^3 = 512 cells
constexpr int NCELL = GC * GC * GC;   // 512
constexpr int NSC = 64;               // 32-wide supercells -> 4^3
constexpr int CAP = 3072;             // SMEM candidate capacity (avg region ~350)
constexpr int TMAIN = 256;
constexpr int TBIN  = 512;
constexpr int PPT   = NB / TBIN;      // points per thread in k_bin = 8

// Scratch (device globals: no allocation allowed)
__device__ int g_bstart[B_][NCELL + 1];
__device__ int g_astart[B_][NSC + 1];
__device__ uint32_t g_bpack[B_][NB];  // cell-sorted packed (x|y<<8|z<<16), coords >>4
__device__ int      g_bidx[B_][NB];   // original b index (gather + tie-break)
__device__ uint32_t g_apack[B_][NA];
__device__ int      g_aidx[B_][NA];   // original a row

// ---------------------------------------------------------------------------
// Fused binning: histogram + scan + scatter, one block per batch.
// ---------------------------------------------------------------------------
__global__ __launch_bounds__(TBIN) void k_bin(
    const int* __restrict__ ac, const int* __restrict__ bc)
{
    __shared__ int sm_h[NCELL];        // b-cell histogram, then cursors
    __shared__ int sm_ha[NSC];         // a-supercell histogram, then cursors
    __shared__ int sm_buf[2][NCELL];   // scan double buffer

    const int b = blockIdx.x, t = threadIdx.x;

    if (t < NCELL) sm_h[t] = 0;
    if (t < NSC)   sm_ha[t] = 0;
    __syncthreads();

    // ---- load coords, histogram in SMEM, stash packed values in registers ----
    uint32_t bp[PPT]; int bcell[PPT];
    uint32_t apk[PPT]; int asc[PPT];
    const int* bcb = bc + (size_t)b * NB * 3;
    const int* acb = ac + (size_t)b * NA * 3;
    #pragma unroll
    for (int i = 0; i < PPT; i++) {
        const int m = t + i * TBIN;
        const int* c = bcb + (size_t)m * 3;
        uint32_t x = ((uint32_t)c[0]) >> 4, y = ((uint32_t)c[1]) >> 4, z = ((uint32_t)c[2]) >> 4;
        bp[i] = x | (y << 8) | (z << 16);
        bcell[i] = (int)(x >> 4) + GC * (int)(y >> 4) + GC * GC * (int)(z >> 4);
        atomicAdd(&sm_h[bcell[i]], 1);

        const int* ca = acb + (size_t)m * 3;
        uint32_t ax = ((uint32_t)ca[0]) >> 4, ay = ((uint32_t)ca[1]) >> 4, az = ((uint32_t)ca[2]) >> 4;
        apk[i] = ax | (ay << 8) | (az << 16);
        asc[i] = (int)(ax >> 5) + 4 * (int)(ay >> 5) + 16 * (int)(az >> 5);
        atomicAdd(&sm_ha[asc[i]], 1);
    }
    __syncthreads();

    // ---- inclusive scan of b histogram (512 entries, 512 threads) ----
    int v = (t < NCELL) ? sm_h[t] : 0;
    int src = 0;
    if (t < NCELL) sm_buf[0][t] = v;
    for (int off = 1; off < NCELL; off <<= 1) {
        __syncthreads();
        if (t < NCELL) {
            int x = sm_buf[src][t];
            if (t >= off) x += sm_buf[src][t - off];
            sm_buf[src ^ 1][t] = x;
        }
        src ^= 1;
    }
    __syncthreads();
    if (t < NCELL) {
        const int incl = sm_buf[src][t];
        g_bstart[b][t + 1] = incl;
        sm_h[t] = incl - v;            // exclusive -> cursor
        if (t == 0) g_bstart[b][0] = 0;
    }
    __syncthreads();

    // ---- scan of a histogram (64 entries) ----
    int va = (t < NSC) ? sm_ha[t] : 0;
    src = 0;
    if (t < NSC) sm_buf[0][t] = va;
    for (int off = 1; off < NSC; off <<= 1) {
        __syncthreads();
        if (t < NSC) {
            int x = sm_buf[src][t];
            if (t >= off) x += sm_buf[src][t - off];
            sm_buf[src ^ 1][t] = x;
        }
        src ^= 1;
    }
    __syncthreads();
    if (t < NSC) {
        const int incl = sm_buf[src][t];
        g_astart[b][t + 1] = incl;
        sm_ha[t] = incl - va;
        if (t == 0) g_astart[b][0] = 0;
    }
    __syncthreads();

    // ---- scatter from register stash via SMEM cursors ----
    #pragma unroll
    for (int i = 0; i < PPT; i++) {
        const int m = t + i * TBIN;
        int pos = atomicAdd(&sm_h[bcell[i]], 1);
        g_bpack[b][pos] = bp[i];
        g_bidx[b][pos]  = m;
        int posa = atomicAdd(&sm_ha[asc[i]], 1);
        g_apack[b][posa] = apk[i];
        g_aidx[b][posa]  = m;
    }
}

__device__ __forceinline__ void insert3(uint32_t key, uint32_t& b0, uint32_t& b1, uint32_t& b2) {
    uint32_t t1 = min(b1, max(b0, key));
    uint32_t t2 = min(b2, max(b1, key));
    b0 = min(b0, key);
    b1 = t1;
    b2 = t2;
}

// ---------------------------------------------------------------------------
// Main: grid (NSC, B_, 4), block 256 (8 warps = candidate splits; 32 a/set)
// ---------------------------------------------------------------------------
__global__ __launch_bounds__(TMAIN) void k_main(
    const float* __restrict__ a_feats, const float* __restrict__ b_feats,
    float* __restrict__ out)
{
    __shared__ uint32_t sm_cp[CAP];
    __shared__ int      sm_ci[CAP];
    __shared__ uint32_t sm_top[8][32][3];
    __shared__ int   sm_i[32][3];
    __shared__ float sm_w[32][3];
    __shared__ int   sm_orow[32];
    __shared__ int   sm_rs[16];
    __shared__ int   sm_ro[17];

    const int b = blockIdx.y, scid = blockIdx.x;
    const int tid = threadIdx.x, lane = tid & 31, w = tid >> 5;

    const int astart = g_astart[b][scid], aend = g_astart[b][scid + 1];
    const int abase0 = astart + blockIdx.z * 32;
    if (abase0 >= aend) return;

    // Candidate region: 4x4x4 cells around the supercell (clipped to grid)
    const int sx = scid & 3, sy = (scid >> 2) & 3, sz = scid >> 4;
    const int x0 = max(0, 2 * sx - 1), x1 = min(GC - 1, 2 * sx + 2);
    const int y0 = max(0, 2 * sy - 1), y1 = min(GC - 1, 2 * sy + 2);
    const int z0 = max(0, 2 * sz - 1), z1 = min(GC - 1, 2 * sz + 2);
    const int ny = y1 - y0 + 1, nz = z1 - z0 + 1, nrun = ny * nz;

    // Warp-parallel region setup: each lane one x-run, shfl prefix sum
    if (w == 0) {
        int s = 0, len = 0;
        if (lane < nrun) {
            const int cy = y0 + lane % ny, cz = z0 + lane / ny;
            const int c0 = x0 + GC * cy + GC * GC * cz;
            s = g_bstart[b][c0];
            len = g_bstart[b][c0 + (x1 - x0) + 1] - s;
        }
        int off = len;
        #pragma unroll
        for (int d = 1; d < 32; d <<= 1) {
            int u = __shfl_up_sync(~0u, off, d);
            if (lane >= d) off += u;
        }
        if (lane < nrun) { sm_rs[lane] = s; sm_ro[lane] = off - len; }
        if (lane == 31) sm_ro[nrun] = off;   // total (len=0 past nrun)
    }
    __syncthreads();
    const int total = sm_ro[nrun];
    const int insm  = min(total, CAP);
    for (int r = 0; r < nrun; r++) {
        const int o0 = sm_ro[r], o1 = min(sm_ro[r + 1], insm);
        const int gsrc = sm_rs[r] - o0;
        for (int i = o0 + tid; i < o1; i += TMAIN) {
            sm_cp[i] = g_bpack[b][gsrc + i];
            sm_ci[i] = g_bidx[b][gsrc + i];
        }
    }
    // Pad to multiple of 4 with keys larger than any real key
    const int nq = (insm + 3) >> 2;
    for (int i = insm + tid; i < nq * 4; i += TMAIN) {
        sm_cp[i] = 0xFF000000u;
        sm_ci[i] = 0;
    }
    __syncthreads();

    for (int abase = abase0; abase < aend; abase += (int)gridDim.z * 32) {
        const int ap = abase + lane;
        const bool valid = ap < aend;
        const uint32_t pa = valid ? g_apack[b][ap] : 0u;
        uint32_t b0 = ~0u, b1 = ~0u, b2 = ~0u;

        const uint4* cp4 = (const uint4*)sm_cp;
        const int4*  ci4 = (const int4*)sm_ci;
        for (int q = w; q < nq; q += 8) {
            const uint4 c  = cp4[q];     // broadcast across lanes
            const int4  mi = ci4[q];
            uint32_t v, d2;
            v = __vabsdiffu4(pa, c.x); d2 = __dp4a(v, v, 0u);
            insert3(d2 * 4096u + (uint32_t)mi.x, b0, b1, b2);
            v = __vabsdiffu4(pa, c.y); d2 = __dp4a(v, v, 0u);
            insert3(d2 * 4096u + (uint32_t)mi.y, b0, b1, b2);
            v = __vabsdiffu4(pa, c.z); d2 = __dp4a(v, v, 0u);
            insert3(d2 * 4096u + (uint32_t)mi.z, b0, b1, b2);
            v = __vabsdiffu4(pa, c.w); d2 = __dp4a(v, v, 0u);
            insert3(d2 * 4096u + (uint32_t)mi.w, b0, b1, b2);
        }
        if (total > insm) {  // overflow remainder: scan from global (broadcast)
            for (int r = 0; r < nrun; r++) {
                const int o0 = sm_ro[r], o1 = sm_ro[r + 1];
                const int gsrc = sm_rs[r] - o0;
                for (int i = max(o0, insm) + w; i < o1; i += 8) {
                    const uint32_t cc = g_bpack[b][gsrc + i];
                    const uint32_t mm = (uint32_t)g_bidx[b][gsrc + i];
                    const uint32_t vv = __vabsdiffu4(pa, cc);
                    const uint32_t d2 = __dp4a(vv, vv, 0u);
                    insert3(d2 * 4096u + mm, b0, b1, b2);
                }
            }
        }
        sm_top[w][lane][0] = b0; sm_top[w][lane][1] = b1; sm_top[w][lane][2] = b2;
        __syncthreads();

        if (w == 0) {
            #pragma unroll
            for (int ss = 1; ss < 8; ss++)
                #pragma unroll
                for (int k = 0; k < 3; k++)
                    insert3(sm_top[ss][lane][k], b0, b1, b2);

            // Exactness: region covers ball(a, 16). If 3rd-best d2 >= 256,
            // exact full scan for this lane (astronomically rare).
            if (valid && (b2 >> 12) >= 256u) {
                b0 = b1 = b2 = ~0u;
                for (int m = 0; m < NB; m++) {
                    const uint32_t vv = __vabsdiffu4(pa, g_bpack[b][m]);
                    const uint32_t d2 = __dp4a(vv, vv, 0u);
                    insert3(d2 * 4096u + (uint32_t)g_bidx[b][m], b0, b1, b2);
                }
            }
            const uint32_t keys[3] = {b0, b1, b2};
            #pragma unroll
            for (int k = 0; k < 3; k++) {
                const uint32_t d2 = keys[k] >> 12;
                sm_i[lane][k] = (int)(keys[k] & 0xFFFu);
                const float dist = sqrtf((float)d2) * (1.0f / 128.0f);
                sm_w[lane][k] = fmaxf(0.5f - dist, 0.0f);
            }
            sm_orow[lane] = valid ? g_aidx[b][ap] : 0;
        }
        __syncthreads();

        // Fused epilogue: out[row] = concat(a_feats[row], sum_k w_k * b_feats[i_k])
        const int nval = min(32, aend - abase);
        const float* bf = b_feats + (size_t)b * NB * D_;
        for (int u = tid; u < nval * 32; u += TMAIN) {
            const int r = u >> 5, c4 = u & 31;
            const int orow = sm_orow[r];
            float4 val;
            if (c4 < 16) {
                val = ((const float4*)(a_feats + ((size_t)b * NA + orow) * D_))[c4];
            } else {
                const int cc = c4 - 16;
                const float4 f0 = ((const float4*)(bf + (size_t)sm_i[r][0] * D_))[cc];
                const float4 f1 = ((const float4*)(bf + (size_t)sm_i[r][1] * D_))[cc];
                const float4 f2 = ((const float4*)(bf + (size_t)sm_i[r][2] * D_))[cc];
                const float w0 = sm_w[r][0], w1 = sm_w[r][1], w2 = sm_w[r][2];
                val.x = w0 * f0.x + w1 * f1.x + w2 * f2.x;
                val.y = w0 * f0.y + w1 * f1.y + w2 * f2.y;
                val.z = w0 * f0.z + w1 * f1.z + w2 * f2.z;
                val.w = w0 * f0.w + w1 * f1.w + w2 * f2.w;
            }
            ((float4*)(out + ((size_t)b * NA + orow) * 2 * D_))[c4] = val;
        }
        __syncthreads();  // protect SMEM reuse for next a-set
    }
}

extern "C" void kernel_launch(void* const* d_in, const int* in_sizes, int n_in,
                              void* d_out, int out_size)
{
    const float* a_feats  = (const float*)d_in[0];
    const float* b_feats  = (const float*)d_in[1];
    const int*   a_coords = (const int*)d_in[2];
    const int*   b_coords = (const int*)d_in[3];
    float*       out      = (float*)d_out;

    k_bin<<<B_, TBIN>>>(a_coords, b_coords);
    dim3 grid(NSC, B_, 4);
    k_main<<<grid, TMAIN>>>(a_feats, b_feats, out);
}